// round 15
// baseline (speedup 1.0000x reference)
#include <cuda_runtime.h>
#include <cuda_fp16.h>

#define N_NODESC 100000
#define N_EDGESC 1600000
#define IN_CH    128
#define NH       64
#define NH2      32
#define OUT_CHC  40

#define SCAN_CHUNK 1024
#define SCAN_NBLK  ((N_NODESC + SCAN_CHUNK - 1) / SCAN_CHUNK)   // 98

typedef unsigned long long u64b;

// ---------------- f32x2 packed helpers (bit-exact fp32, 2 MACs/instr) ----------------
__device__ __forceinline__ void ffma2(u64b& d, u64b a, u64b b) {
    asm("fma.rn.f32x2 %0, %1, %2, %0;" : "+l"(d) : "l"(a), "l"(b));
}
__device__ __forceinline__ float2 unpack2(u64b v) {
    float2 f; asm("mov.b64 {%0, %1}, %2;" : "=f"(f.x), "=f"(f.y) : "l"(v)); return f;
}
union F4U { float4 v; u64b d[2]; };

// ---------------- scratch ----------------
__device__ int     g_is64;
__device__ int     g_deg[N_NODESC];
__device__ int     g_rowptr[N_NODESC + 1];
__device__ int     g_cursor[N_NODESC];
__device__ int     g_bsum[SCAN_NBLK];
__device__ int     g_boff[SCAN_NBLK];
__device__ int     g_src[N_EDGESC + 8];
__device__ float   g_dinv[N_NODESC];
__device__ __half2 g_h0h[N_NODESC * NH2];        // fp16 residual (unscaled)
__device__ __half2 g_h016[N_NODESC * NH2];       // fp16, pre-scaled by dinv[node]
__device__ __half2 g_hA16[N_NODESC * NH2];
__device__ __half2 g_hB16[N_NODESC * NH2];

// ---------------- dtype detect + zero degree ----------------
__global__ void k_init(const int* __restrict__ ei) {
    int i = blockIdx.x * blockDim.x + threadIdx.x;
    if (i < N_NODESC) g_deg[i] = 0;
    if (blockIdx.x == 0 && threadIdx.x == 0) {
        int nz = 0;
        for (int j = 1; j < 512; j += 2) nz |= ei[j];
        g_is64 = (nz == 0) ? 1 : 0;
    }
}

// decode 2 edges per thread; histogram only
__global__ void k_degree(const int* __restrict__ ei) {
    int t = blockIdx.x * blockDim.x + threadIdx.x;
    if (t >= N_EDGESC / 2) return;
    int c0, c1;
    if (g_is64) {
        int4 cc = __ldg((const int4*)&ei[2 * N_EDGESC + 4 * t]);
        c0 = cc.x; c1 = cc.z;
    } else {
        int2 cc = __ldg((const int2*)&ei[N_EDGESC + 2 * t]);
        c0 = cc.x; c1 = cc.y;
    }
    if ((unsigned)c0 >= N_NODESC) c0 = 0;
    if ((unsigned)c1 >= N_NODESC) c1 = 0;
    atomicAdd(&g_deg[c0], 1);
    atomicAdd(&g_deg[c1], 1);
}

__global__ void k_scan_bsum() {
    __shared__ int s[SCAN_CHUNK];
    int t = threadIdx.x;
    int i = blockIdx.x * SCAN_CHUNK + t;
    int d = (i < N_NODESC) ? g_deg[i] : 0;
    if (i < N_NODESC) g_dinv[i] = (d > 0) ? rsqrtf((float)d) : 0.0f;
    s[t] = d;
    __syncthreads();
    for (int off = SCAN_CHUNK / 2; off > 0; off >>= 1) {
        if (t < off) s[t] += s[t + off];
        __syncthreads();
    }
    if (t == 0) g_bsum[blockIdx.x] = s[0];
}

__global__ void k_scan_top() {
    __shared__ int s[128];
    int t = threadIdx.x;
    s[t] = (t < SCAN_NBLK) ? g_bsum[t] : 0;
    __syncthreads();
    if (t == 0) {
        int acc = 0;
        for (int b = 0; b < SCAN_NBLK; b++) { int v = s[b]; s[b] = acc; acc += v; }
        g_rowptr[N_NODESC] = N_EDGESC;
    }
    __syncthreads();
    if (t < SCAN_NBLK) g_boff[t] = s[t];
}

__global__ void k_scan_within() {
    __shared__ int s[SCAN_CHUNK];
    int t = threadIdx.x;
    int i = blockIdx.x * SCAN_CHUNK + t;
    int v = (i < N_NODESC) ? g_deg[i] : 0;
    s[t] = v;
    __syncthreads();
    for (int off = 1; off < SCAN_CHUNK; off <<= 1) {
        int x = (t >= off) ? s[t - off] : 0;
        __syncthreads();
        s[t] += x;
        __syncthreads();
    }
    int excl = s[t] - v + g_boff[blockIdx.x];
    if (i < N_NODESC) { g_rowptr[i] = excl; g_cursor[i] = excl; }
}

// decode 2 edges per thread directly from ei; src index only
__global__ void k_scatter(const int* __restrict__ ei) {
    int t = blockIdx.x * blockDim.x + threadIdx.x;
    if (t >= N_EDGESC / 2) return;
    int r0, c0, r1, c1;
    if (g_is64) {
        int4 rr = __ldg((const int4*)&ei[4 * t]);
        int4 cc = __ldg((const int4*)&ei[2 * N_EDGESC + 4 * t]);
        r0 = rr.x; r1 = rr.z; c0 = cc.x; c1 = cc.z;
    } else {
        int2 rr = __ldg((const int2*)&ei[2 * t]);
        int2 cc = __ldg((const int2*)&ei[N_EDGESC + 2 * t]);
        r0 = rr.x; r1 = rr.y; c0 = cc.x; c1 = cc.y;
    }
    if ((unsigned)r0 >= N_NODESC) r0 = 0;
    if ((unsigned)r1 >= N_NODESC) r1 = 0;
    if ((unsigned)c0 >= N_NODESC) c0 = 0;
    if ((unsigned)c1 >= N_NODESC) c1 = 0;
    int p0 = atomicAdd(&g_cursor[c0], 1);
    if ((unsigned)p0 < N_EDGESC) g_src[p0] = r0;
    int p1 = atomicAdd(&g_cursor[c1], 1);
    if ((unsigned)p1 < N_EDGESC) g_src[p1] = r1;
}

// ---------------- fc1: persistent blocks, mma.sync fp16 ----------------
#define FC1_XS 136      // padded row stride in halves
#define FC1_NTILES ((N_NODESC + 63) / 64)   // 1563
__global__ __launch_bounds__(256) void k_fc1(const float* __restrict__ x,
                                             const float* __restrict__ w,
                                             const float* __restrict__ b) {
    __shared__ __half sX[64 * FC1_XS];      // 17.4 KB fp16 x tile
    __shared__ __half sW[64 * FC1_XS];      // 17.4 KB fp16 W (staged ONCE)
    __shared__ float  sBias[NH];
    __shared__ float  sDinv[64];

    int tid = threadIdx.x;

    // stage W (fp32 -> fp16) once per block
    {
        int row = tid >> 2, seg = tid & 3;
        #pragma unroll
        for (int it = 0; it < 4; it++) {
            int k = seg * 32 + it * 8;
            float4 v0 = __ldg((const float4*)&w[row * IN_CH + k]);
            float4 v1 = __ldg((const float4*)&w[row * IN_CH + k + 4]);
            __half2 h0 = __floats2half2_rn(v0.x, v0.y);
            __half2 h1 = __floats2half2_rn(v0.z, v0.w);
            __half2 h2 = __floats2half2_rn(v1.x, v1.y);
            __half2 h3 = __floats2half2_rn(v1.z, v1.w);
            uint4 u = make_uint4(*(unsigned*)&h0, *(unsigned*)&h1,
                                 *(unsigned*)&h2, *(unsigned*)&h3);
            *(uint4*)&sW[row * FC1_XS + k] = u;
        }
    }
    if (tid < NH) sBias[tid] = b[tid];

    int warp = tid >> 5, lane = tid & 31;
    int g = lane >> 2, t = lane & 3;
    int m0 = (warp & 3) * 16;
    int nu = warp >> 2;

    for (int tile = blockIdx.x; tile < FC1_NTILES; tile += gridDim.x) {
        int base = tile * 64;
        __syncthreads();    // protect sX/sDinv from previous iteration's readers
        // stage x (fp32 -> fp16), 64 rows, clamp OOB
        {
            int row = tid >> 2, seg = tid & 3;
            long grow = (base + row < N_NODESC) ? (long)(base + row) : (long)(N_NODESC - 1);
            #pragma unroll
            for (int it = 0; it < 4; it++) {
                int k = seg * 32 + it * 8;
                float4 v0 = __ldg((const float4*)&x[grow * IN_CH + k]);
                float4 v1 = __ldg((const float4*)&x[grow * IN_CH + k + 4]);
                __half2 h0 = __floats2half2_rn(v0.x, v0.y);
                __half2 h1 = __floats2half2_rn(v0.z, v0.w);
                __half2 h2 = __floats2half2_rn(v1.x, v1.y);
                __half2 h3 = __floats2half2_rn(v1.z, v1.w);
                uint4 u = make_uint4(*(unsigned*)&h0, *(unsigned*)&h1,
                                     *(unsigned*)&h2, *(unsigned*)&h3);
                *(uint4*)&sX[row * FC1_XS + k] = u;
            }
        }
        if (tid < 64) sDinv[tid] = (base + tid < N_NODESC) ? g_dinv[base + tid] : 0.f;
        __syncthreads();

        float d[2][2][4];
        #pragma unroll
        for (int u = 0; u < 2; u++)
            #pragma unroll
            for (int jm = 0; jm < 2; jm++)
                #pragma unroll
                for (int q = 0; q < 4; q++) d[u][jm][q] = 0.f;

        #pragma unroll
        for (int ks = 0; ks < 8; ks++) {
            int k0 = ks * 16;
            unsigned a0 = *(const unsigned*)&sX[(m0 + g) * FC1_XS + k0 + 2 * t];
            unsigned a1 = *(const unsigned*)&sX[(m0 + g + 8) * FC1_XS + k0 + 2 * t];
            unsigned a2 = *(const unsigned*)&sX[(m0 + g) * FC1_XS + k0 + 2 * t + 8];
            unsigned a3 = *(const unsigned*)&sX[(m0 + g + 8) * FC1_XS + k0 + 2 * t + 8];
            #pragma unroll
            for (int u = 0; u < 2; u++) {
                #pragma unroll
                for (int jm = 0; jm < 2; jm++) {
                    int n8 = nu * 32 + u * 16 + jm * 8;
                    unsigned b0 = *(const unsigned*)&sW[(n8 + g) * FC1_XS + k0 + 2 * t];
                    unsigned b1 = *(const unsigned*)&sW[(n8 + g) * FC1_XS + k0 + 2 * t + 8];
                    asm volatile(
                        "mma.sync.aligned.m16n8k16.row.col.f32.f16.f16.f32 "
                        "{%0,%1,%2,%3}, {%4,%5,%6,%7}, {%8,%9}, {%0,%1,%2,%3};"
                        : "+f"(d[u][jm][0]), "+f"(d[u][jm][1]),
                          "+f"(d[u][jm][2]), "+f"(d[u][jm][3])
                        : "r"(a0), "r"(a1), "r"(a2), "r"(a3), "r"(b0), "r"(b1));
                }
            }
        }

        int node0 = base + m0 + g;
        int node1 = node0 + 8;
        float dv0 = sDinv[m0 + g], dv1 = sDinv[m0 + g + 8];
        #pragma unroll
        for (int u = 0; u < 2; u++) {
            #pragma unroll
            for (int jm = 0; jm < 2; jm++) {
                int j0 = nu * 32 + u * 16 + jm * 8 + 2 * t;
                float2 bb = *(const float2*)&sBias[j0];
                float r00 = fmaxf(d[u][jm][0] + bb.x, 0.f);
                float r01 = fmaxf(d[u][jm][1] + bb.y, 0.f);
                float r10 = fmaxf(d[u][jm][2] + bb.x, 0.f);
                float r11 = fmaxf(d[u][jm][3] + bb.y, 0.f);
                if (node0 < N_NODESC) {
                    g_h0h[node0 * NH2 + (j0 >> 1)]  = __floats2half2_rn(r00, r01);
                    g_h016[node0 * NH2 + (j0 >> 1)] = __floats2half2_rn(r00 * dv0, r01 * dv0);
                }
                if (node1 < N_NODESC) {
                    g_h0h[node1 * NH2 + (j0 >> 1)]  = __floats2half2_rn(r10, r11);
                    g_h016[node1 * NH2 + (j0 >> 1)] = __floats2half2_rn(r10 * dv1, r11 * dv1);
                }
            }
        }
    }
}

// ---------------- fused GCN2 layer: persistent blocks, mma.sync matmul ----------------
// Gather: R12 straight-line form (FROZEN). W^T staged once per block.
#define MIX_S 72
#define LAYER_NTILES ((N_NODESC + 63) / 64)     // 1563
__global__ __launch_bounds__(256) void k_layer(const __half2* __restrict__ hin2,
                                               const __half2* __restrict__ h0h,
                                               const float* __restrict__ W,
                                               __half2* __restrict__ hout2,
                                               int scale_out) {
    __shared__ __half sMixA[64 * MIX_S];    // 9.2 KB [node][k]
    __shared__ __half sWT[64 * MIX_S];      // 9.2 KB [j][k] (staged ONCE)

    // stage W^T fp16 once: sWT[j][k] = W[k][j]
    for (int i = threadIdx.x; i < NH * NH; i += 256) {
        int k = i >> 6, j = i & 63;
        sWT[j * MIX_S + k] = __float2half(W[i]);
    }

    int warp = threadIdx.x >> 5, lane = threadIdx.x & 31;
    int g = lane >> 2, t = lane & 3;
    int m0 = (warp & 3) * 16;
    int nu = warp >> 2;

    for (int tile = blockIdx.x; tile < LAYER_NTILES; tile += gridDim.x) {
        int nodebase = tile * 64;
        __syncthreads();    // protect sMixA from previous iteration's mma readers

        // gather 8 nodes per warp (R12 form)
        for (int m = 0; m < 8; m++) {
            int nl = warp * 8 + m;
            int node = nodebase + nl;
            float ax0 = 0.f, ay0 = 0.f, ax1 = 0.f, ay1 = 0.f;
            float mx = 0.f, my = 0.f;
            if (node < N_NODESC) {
                int s = g_rowptr[node], e = g_rowptr[node + 1];
                int i = s;
                for (; i + 8 <= e; i += 8) {
                    int s0 = __ldg(&g_src[i]);
                    int s1 = __ldg(&g_src[i + 1]);
                    int s2 = __ldg(&g_src[i + 2]);
                    int s3 = __ldg(&g_src[i + 3]);
                    int s4 = __ldg(&g_src[i + 4]);
                    int s5 = __ldg(&g_src[i + 5]);
                    int s6 = __ldg(&g_src[i + 6]);
                    int s7 = __ldg(&g_src[i + 7]);
                    float2 v0 = __half22float2(__ldg(&hin2[s0 * NH2 + lane]));
                    float2 v1 = __half22float2(__ldg(&hin2[s1 * NH2 + lane]));
                    float2 v2 = __half22float2(__ldg(&hin2[s2 * NH2 + lane]));
                    float2 v3 = __half22float2(__ldg(&hin2[s3 * NH2 + lane]));
                    float2 v4 = __half22float2(__ldg(&hin2[s4 * NH2 + lane]));
                    float2 v5 = __half22float2(__ldg(&hin2[s5 * NH2 + lane]));
                    float2 v6 = __half22float2(__ldg(&hin2[s6 * NH2 + lane]));
                    float2 v7 = __half22float2(__ldg(&hin2[s7 * NH2 + lane]));
                    ax0 += v0.x; ay0 += v0.y;
                    ax1 += v1.x; ay1 += v1.y;
                    ax0 += v2.x; ay0 += v2.y;
                    ax1 += v3.x; ay1 += v3.y;
                    ax0 += v4.x; ay0 += v4.y;
                    ax1 += v5.x; ay1 += v5.y;
                    ax0 += v6.x; ay0 += v6.y;
                    ax1 += v7.x; ay1 += v7.y;
                }
                if (i + 4 <= e) {
                    int s0 = __ldg(&g_src[i]);
                    int s1 = __ldg(&g_src[i + 1]);
                    int s2 = __ldg(&g_src[i + 2]);
                    int s3 = __ldg(&g_src[i + 3]);
                    float2 v0 = __half22float2(__ldg(&hin2[s0 * NH2 + lane]));
                    float2 v1 = __half22float2(__ldg(&hin2[s1 * NH2 + lane]));
                    float2 v2 = __half22float2(__ldg(&hin2[s2 * NH2 + lane]));
                    float2 v3 = __half22float2(__ldg(&hin2[s3 * NH2 + lane]));
                    ax0 += v0.x; ay0 += v0.y;
                    ax1 += v1.x; ay1 += v1.y;
                    ax0 += v2.x; ay0 += v2.y;
                    ax1 += v3.x; ay1 += v3.y;
                    i += 4;
                }
                for (; i < e; i++) {
                    int s0 = __ldg(&g_src[i]);
                    float2 v0 = __half22float2(__ldg(&hin2[s0 * NH2 + lane]));
                    ax0 += v0.x; ay0 += v0.y;
                }
                float ax = ax0 + ax1, ay = ay0 + ay1;
                float2 h0v = __half22float2(__ldg(&h0h[node * NH2 + lane]));
                float dv = g_dinv[node];
                mx = fmaf(0.9f * dv, ax, 0.1f * h0v.x);
                my = fmaf(0.9f * dv, ay, 0.1f * h0v.y);
            }
            *(__half2*)&sMixA[nl * MIX_S + 2 * lane] = __floats2half2_rn(mx, my);
        }
        __syncthreads();

        // mma matmul: D[64 nodes][64 j] = sMixA @ sWT^T
        float d[2][2][4];
        #pragma unroll
        for (int u = 0; u < 2; u++)
            #pragma unroll
            for (int jm = 0; jm < 2; jm++)
                #pragma unroll
                for (int q = 0; q < 4; q++) d[u][jm][q] = 0.f;

        #pragma unroll
        for (int ks = 0; ks < 4; ks++) {
            int k0 = ks * 16;
            unsigned a0 = *(const unsigned*)&sMixA[(m0 + g) * MIX_S + k0 + 2 * t];
            unsigned a1 = *(const unsigned*)&sMixA[(m0 + g + 8) * MIX_S + k0 + 2 * t];
            unsigned a2 = *(const unsigned*)&sMixA[(m0 + g) * MIX_S + k0 + 2 * t + 8];
            unsigned a3 = *(const unsigned*)&sMixA[(m0 + g + 8) * MIX_S + k0 + 2 * t + 8];
            #pragma unroll
            for (int u = 0; u < 2; u++) {
                #pragma unroll
                for (int jm = 0; jm < 2; jm++) {
                    int n8 = nu * 32 + u * 16 + jm * 8;
                    unsigned b0 = *(const unsigned*)&sWT[(n8 + g) * MIX_S + k0 + 2 * t];
                    unsigned b1 = *(const unsigned*)&sWT[(n8 + g) * MIX_S + k0 + 2 * t + 8];
                    asm volatile(
                        "mma.sync.aligned.m16n8k16.row.col.f32.f16.f16.f32 "
                        "{%0,%1,%2,%3}, {%4,%5,%6,%7}, {%8,%9}, {%0,%1,%2,%3};"
                        : "+f"(d[u][jm][0]), "+f"(d[u][jm][1]),
                          "+f"(d[u][jm][2]), "+f"(d[u][jm][3])
                        : "r"(a0), "r"(a1), "r"(a2), "r"(a3), "r"(b0), "r"(b1));
                }
            }
        }

        // epilogue: relu + optional dinv scale + fp16 store
        int node0 = nodebase + m0 + g;
        int node1 = node0 + 8;
        float sc0 = 1.f, sc1 = 1.f;
        if (scale_out) {
            if (node0 < N_NODESC) sc0 = g_dinv[node0];
            if (node1 < N_NODESC) sc1 = g_dinv[node1];
        }
        #pragma unroll
        for (int u = 0; u < 2; u++) {
            #pragma unroll
            for (int jm = 0; jm < 2; jm++) {
                int j0 = nu * 32 + u * 16 + jm * 8 + 2 * t;
                if (node0 < N_NODESC) {
                    float o0 = fmaxf(d[u][jm][0], 0.f) * sc0;
                    float o1 = fmaxf(d[u][jm][1], 0.f) * sc0;
                    hout2[node0 * NH2 + (j0 >> 1)] = __floats2half2_rn(o0, o1);
                }
                if (node1 < N_NODESC) {
                    float o0 = fmaxf(d[u][jm][2], 0.f) * sc1;
                    float o1 = fmaxf(d[u][jm][3], 0.f) * sc1;
                    hout2[node1 * NH2 + (j0 >> 1)] = __floats2half2_rn(o0, o1);
                }
            }
        }
    }
}

// ---------------- fc2: out = h @ W2^T + b2, split-K f32x2 ----------------
#define SW2S 66
#define SH2S 66
__global__ __launch_bounds__(320, 4) void k_fc2(const __half2* __restrict__ hin2,
                                                const float* __restrict__ w,
                                                const float* __restrict__ b,
                                                float* __restrict__ out) {
    __shared__ float sW[OUT_CHC * SW2S];
    __shared__ float sH[8 * SH2S];
    __shared__ float sB[OUT_CHC];
    for (int i = threadIdx.x; i < OUT_CHC * NH / 2; i += 320) {
        int j = i >> 5, kp = i & 31;
        *(float2*)&sW[j * SW2S + 2 * kp] = *(const float2*)&w[j * NH + 2 * kp];
    }
    if (threadIdx.x < OUT_CHC) sB[threadIdx.x] = b[threadIdx.x];
    __syncthreads();

    int tn = threadIdx.x / OUT_CHC;
    int j  = threadIdx.x % OUT_CHC;
    const int ngroups = N_NODESC / 8;

    for (int g = blockIdx.x; g < ngroups; g += gridDim.x) {
        int base = g * 8;
        __syncthreads();
        for (int i = threadIdx.x; i < 8 * NH2; i += 320) {
            int n = i >> 5, k2 = i & 31;
            float2 v = __half22float2(hin2[(base + n) * NH2 + k2]);
            *(float2*)&sH[n * SH2S + 2 * k2] = v;
        }
        __syncthreads();
        u64b acc = 0ULL;
        #pragma unroll 8
        for (int kp = 0; kp < NH / 2; kp++) {
            u64b a  = *(const u64b*)&sH[tn * SH2S + 2 * kp];
            u64b wv = *(const u64b*)&sW[j * SW2S + 2 * kp];
            ffma2(acc, a, wv);
        }
        float2 f = unpack2(acc);
        out[(long)(base + tn) * OUT_CHC + j] = f.x + f.y + sB[j];
    }
}

// ---------------- launch ----------------
extern "C" void kernel_launch(void* const* d_in, const int* in_sizes, int n_in,
                              void* d_out, int out_size) {
    const float* x      = (const float*)d_in[0];
    const int*   ei     = (const int*)d_in[1];
    const float* fc1_w  = (const float*)d_in[3];
    const float* fc1_b  = (const float*)d_in[4];
    const float* conv_w = (const float*)d_in[5];
    const float* fc2_w  = (const float*)d_in[6];
    const float* fc2_b  = (const float*)d_in[7];
    float*       out    = (float*)d_out;

    const int nb_nodes  = (N_NODESC + 255) / 256;
    const int nb_epairs = (N_EDGESC / 2 + 255) / 256;

    k_init<<<nb_nodes, 256>>>(ei);              // 0
    k_degree<<<nb_epairs, 256>>>(ei);           // 1
    k_scan_bsum<<<SCAN_NBLK, SCAN_CHUNK>>>();   // 2 (also dinv)
    k_fc1<<<740, 256>>>(x, fc1_w, fc1_b);       // 3 (profiled slot, persistent)
    k_scan_top<<<1, 128>>>();
    k_scan_within<<<SCAN_NBLK, SCAN_CHUNK>>>();
    k_scatter<<<nb_epairs, 256>>>(ei);

    __half2* h0h; __half2* h016; __half2* hA16; __half2* hB16;
    cudaGetSymbolAddress((void**)&h0h,  g_h0h);
    cudaGetSymbolAddress((void**)&h016, g_h016);
    cudaGetSymbolAddress((void**)&hA16, g_hA16);
    cudaGetSymbolAddress((void**)&hB16, g_hB16);

    k_layer<<<782, 256>>>(h016, h0h, conv_w + 0 * NH * NH, hA16, 1);
    k_layer<<<782, 256>>>(hA16, h0h, conv_w + 1 * NH * NH, hB16, 1);
    k_layer<<<782, 256>>>(hB16, h0h, conv_w + 2 * NH * NH, hA16, 1);
    k_layer<<<782, 256>>>(hA16, h0h, conv_w + 3 * NH * NH, hB16, 0);

    k_fc2<<<592, 320>>>(hB16, fc2_w, fc2_b, out);
}

// round 16
// speedup vs baseline: 1.1995x; 1.1995x over previous
#include <cuda_runtime.h>
#include <cuda_fp16.h>

#define N_NODESC 100000
#define N_EDGESC 1600000
#define IN_CH    128
#define NH       64
#define NH2      32
#define OUT_CHC  40

#define SCAN_CHUNK 1024
#define SCAN_NBLK  ((N_NODESC + SCAN_CHUNK - 1) / SCAN_CHUNK)   // 98

typedef unsigned long long u64b;

// ---------------- scratch ----------------
__device__ int     g_is64;
__device__ int     g_deg[N_NODESC];
__device__ int     g_rowptr[N_NODESC + 1];
__device__ int     g_cursor[N_NODESC];
__device__ int     g_bsum[SCAN_NBLK];
__device__ int     g_boff[SCAN_NBLK];
__device__ int     g_src[N_EDGESC + 8];
__device__ float   g_dinv[N_NODESC];
__device__ __half2 g_h0h[N_NODESC * NH2];        // fp16 residual (unscaled)
__device__ __half2 g_h016[N_NODESC * NH2];       // fp16, pre-scaled by dinv[node]
__device__ __half2 g_hA16[N_NODESC * NH2];
__device__ __half2 g_hB16[N_NODESC * NH2];

// ---------------- dtype detect + zero degree ----------------
__global__ void k_init(const int* __restrict__ ei) {
    int i = blockIdx.x * blockDim.x + threadIdx.x;
    if (i < N_NODESC) g_deg[i] = 0;
    if (blockIdx.x == 0 && threadIdx.x == 0) {
        int nz = 0;
        for (int j = 1; j < 512; j += 2) nz |= ei[j];
        g_is64 = (nz == 0) ? 1 : 0;
    }
}

// 4 edges per thread; histogram only
__global__ void k_degree(const int* __restrict__ ei) {
    int t = blockIdx.x * blockDim.x + threadIdx.x;
    if (t >= N_EDGESC / 4) return;
    int c[4];
    if (g_is64) {
        int4 a = __ldg((const int4*)&ei[2 * N_EDGESC + 8 * t]);
        int4 b = __ldg((const int4*)&ei[2 * N_EDGESC + 8 * t + 4]);
        c[0] = a.x; c[1] = a.z; c[2] = b.x; c[3] = b.z;
    } else {
        int4 a = __ldg((const int4*)&ei[N_EDGESC + 4 * t]);
        c[0] = a.x; c[1] = a.y; c[2] = a.z; c[3] = a.w;
    }
    #pragma unroll
    for (int q = 0; q < 4; q++) {
        int cc = ((unsigned)c[q] >= N_NODESC) ? 0 : c[q];
        atomicAdd(&g_deg[cc], 1);
    }
}

__global__ void k_scan_bsum() {
    __shared__ int s[SCAN_CHUNK];
    int t = threadIdx.x;
    int i = blockIdx.x * SCAN_CHUNK + t;
    int d = (i < N_NODESC) ? g_deg[i] : 0;
    if (i < N_NODESC) g_dinv[i] = (d > 0) ? rsqrtf((float)d) : 0.0f;
    s[t] = d;
    __syncthreads();
    for (int off = SCAN_CHUNK / 2; off > 0; off >>= 1) {
        if (t < off) s[t] += s[t + off];
        __syncthreads();
    }
    if (t == 0) g_bsum[blockIdx.x] = s[0];
}

__global__ void k_scan_top() {
    __shared__ int s[128];
    int t = threadIdx.x;
    s[t] = (t < SCAN_NBLK) ? g_bsum[t] : 0;
    __syncthreads();
    if (t == 0) {
        int acc = 0;
        for (int b = 0; b < SCAN_NBLK; b++) { int v = s[b]; s[b] = acc; acc += v; }
        g_rowptr[N_NODESC] = N_EDGESC;
    }
    __syncthreads();
    if (t < SCAN_NBLK) g_boff[t] = s[t];
}

__global__ void k_scan_within() {
    __shared__ int s[SCAN_CHUNK];
    int t = threadIdx.x;
    int i = blockIdx.x * SCAN_CHUNK + t;
    int v = (i < N_NODESC) ? g_deg[i] : 0;
    s[t] = v;
    __syncthreads();
    for (int off = 1; off < SCAN_CHUNK; off <<= 1) {
        int x = (t >= off) ? s[t - off] : 0;
        __syncthreads();
        s[t] += x;
        __syncthreads();
    }
    int excl = s[t] - v + g_boff[blockIdx.x];
    if (i < N_NODESC) { g_rowptr[i] = excl; g_cursor[i] = excl; }
}

// 4 edges per thread directly from ei; src index only
__global__ void k_scatter(const int* __restrict__ ei) {
    int t = blockIdx.x * blockDim.x + threadIdx.x;
    if (t >= N_EDGESC / 4) return;
    int r[4], c[4];
    if (g_is64) {
        int4 ra = __ldg((const int4*)&ei[8 * t]);
        int4 rb = __ldg((const int4*)&ei[8 * t + 4]);
        int4 ca = __ldg((const int4*)&ei[2 * N_EDGESC + 8 * t]);
        int4 cb = __ldg((const int4*)&ei[2 * N_EDGESC + 8 * t + 4]);
        r[0] = ra.x; r[1] = ra.z; r[2] = rb.x; r[3] = rb.z;
        c[0] = ca.x; c[1] = ca.z; c[2] = cb.x; c[3] = cb.z;
    } else {
        int4 ra = __ldg((const int4*)&ei[4 * t]);
        int4 ca = __ldg((const int4*)&ei[N_EDGESC + 4 * t]);
        r[0] = ra.x; r[1] = ra.y; r[2] = ra.z; r[3] = ra.w;
        c[0] = ca.x; c[1] = ca.y; c[2] = ca.z; c[3] = ca.w;
    }
    #pragma unroll
    for (int q = 0; q < 4; q++) {
        int rr = ((unsigned)r[q] >= N_NODESC) ? 0 : r[q];
        int cc = ((unsigned)c[q] >= N_NODESC) ? 0 : c[q];
        int p = atomicAdd(&g_cursor[cc], 1);
        if ((unsigned)p < N_EDGESC) g_src[p] = rr;
    }
}

// ---------------- fc1: h = relu(x @ W1^T + b1) via mma.sync fp16 (R14 exact) ----------------
#define FC1_XS 136
__global__ __launch_bounds__(256) void k_fc1(const float* __restrict__ x,
                                             const float* __restrict__ w,
                                             const float* __restrict__ b) {
    __shared__ __half sX[64 * FC1_XS];
    __shared__ __half sW[64 * FC1_XS];
    __shared__ float  sBias[NH];
    __shared__ float  sDinv[64];

    int tid = threadIdx.x;
    int base = blockIdx.x * 64;

    {
        int row = tid >> 2, seg = tid & 3;
        #pragma unroll
        for (int it = 0; it < 4; it++) {
            int k = seg * 32 + it * 8;
            float4 v0 = __ldg((const float4*)&w[row * IN_CH + k]);
            float4 v1 = __ldg((const float4*)&w[row * IN_CH + k + 4]);
            __half2 h0 = __floats2half2_rn(v0.x, v0.y);
            __half2 h1 = __floats2half2_rn(v0.z, v0.w);
            __half2 h2 = __floats2half2_rn(v1.x, v1.y);
            __half2 h3 = __floats2half2_rn(v1.z, v1.w);
            uint4 u = make_uint4(*(unsigned*)&h0, *(unsigned*)&h1,
                                 *(unsigned*)&h2, *(unsigned*)&h3);
            *(uint4*)&sW[row * FC1_XS + k] = u;
        }
    }
    {
        int row = tid >> 2, seg = tid & 3;
        long grow = (base + row < N_NODESC) ? (long)(base + row) : (long)(N_NODESC - 1);
        #pragma unroll
        for (int it = 0; it < 4; it++) {
            int k = seg * 32 + it * 8;
            float4 v0 = __ldg((const float4*)&x[grow * IN_CH + k]);
            float4 v1 = __ldg((const float4*)&x[grow * IN_CH + k + 4]);
            __half2 h0 = __floats2half2_rn(v0.x, v0.y);
            __half2 h1 = __floats2half2_rn(v0.z, v0.w);
            __half2 h2 = __floats2half2_rn(v1.x, v1.y);
            __half2 h3 = __floats2half2_rn(v1.z, v1.w);
            uint4 u = make_uint4(*(unsigned*)&h0, *(unsigned*)&h1,
                                 *(unsigned*)&h2, *(unsigned*)&h3);
            *(uint4*)&sX[row * FC1_XS + k] = u;
        }
    }
    if (tid < NH) sBias[tid] = b[tid];
    if (tid < 64) sDinv[tid] = (base + tid < N_NODESC) ? g_dinv[base + tid] : 0.f;
    __syncthreads();

    int warp = tid >> 5, lane = tid & 31;
    int g = lane >> 2, t = lane & 3;
    int m0 = (warp & 3) * 16;
    int nu = warp >> 2;

    float d[2][2][4];
    #pragma unroll
    for (int u = 0; u < 2; u++)
        #pragma unroll
        for (int jm = 0; jm < 2; jm++)
            #pragma unroll
            for (int q = 0; q < 4; q++) d[u][jm][q] = 0.f;

    #pragma unroll
    for (int ks = 0; ks < 8; ks++) {
        int k0 = ks * 16;
        unsigned a0 = *(const unsigned*)&sX[(m0 + g) * FC1_XS + k0 + 2 * t];
        unsigned a1 = *(const unsigned*)&sX[(m0 + g + 8) * FC1_XS + k0 + 2 * t];
        unsigned a2 = *(const unsigned*)&sX[(m0 + g) * FC1_XS + k0 + 2 * t + 8];
        unsigned a3 = *(const unsigned*)&sX[(m0 + g + 8) * FC1_XS + k0 + 2 * t + 8];
        #pragma unroll
        for (int u = 0; u < 2; u++) {
            #pragma unroll
            for (int jm = 0; jm < 2; jm++) {
                int n8 = nu * 32 + u * 16 + jm * 8;
                unsigned b0 = *(const unsigned*)&sW[(n8 + g) * FC1_XS + k0 + 2 * t];
                unsigned b1 = *(const unsigned*)&sW[(n8 + g) * FC1_XS + k0 + 2 * t + 8];
                asm volatile(
                    "mma.sync.aligned.m16n8k16.row.col.f32.f16.f16.f32 "
                    "{%0,%1,%2,%3}, {%4,%5,%6,%7}, {%8,%9}, {%0,%1,%2,%3};"
                    : "+f"(d[u][jm][0]), "+f"(d[u][jm][1]),
                      "+f"(d[u][jm][2]), "+f"(d[u][jm][3])
                    : "r"(a0), "r"(a1), "r"(a2), "r"(a3), "r"(b0), "r"(b1));
            }
        }
    }

    int node0 = base + m0 + g;
    int node1 = node0 + 8;
    float dv0 = sDinv[m0 + g], dv1 = sDinv[m0 + g + 8];
    #pragma unroll
    for (int u = 0; u < 2; u++) {
        #pragma unroll
        for (int jm = 0; jm < 2; jm++) {
            int j0 = nu * 32 + u * 16 + jm * 8 + 2 * t;
            float2 bb = *(const float2*)&sBias[j0];
            float r00 = fmaxf(d[u][jm][0] + bb.x, 0.f);
            float r01 = fmaxf(d[u][jm][1] + bb.y, 0.f);
            float r10 = fmaxf(d[u][jm][2] + bb.x, 0.f);
            float r11 = fmaxf(d[u][jm][3] + bb.y, 0.f);
            if (node0 < N_NODESC) {
                g_h0h[node0 * NH2 + (j0 >> 1)]  = __floats2half2_rn(r00, r01);
                g_h016[node0 * NH2 + (j0 >> 1)] = __floats2half2_rn(r00 * dv0, r01 * dv0);
            }
            if (node1 < N_NODESC) {
                g_h0h[node1 * NH2 + (j0 >> 1)]  = __floats2half2_rn(r10, r11);
                g_h016[node1 * NH2 + (j0 >> 1)] = __floats2half2_rn(r10 * dv1, r11 * dv1);
            }
        }
    }
}

// ---------------- fused GCN2 layer: R14 exact (gather FROZEN, mma matmul) ----------------
#define MIX_S 72
__global__ __launch_bounds__(256) void k_layer(const __half2* __restrict__ hin2,
                                               const __half2* __restrict__ h0h,
                                               const float* __restrict__ W,
                                               __half2* __restrict__ hout2,
                                               int scale_out) {
    __shared__ __half sMixA[64 * MIX_S];
    __shared__ __half sWT[64 * MIX_S];

    for (int i = threadIdx.x; i < NH * NH; i += 256) {
        int k = i >> 6, j = i & 63;
        sWT[j * MIX_S + k] = __float2half(W[i]);
    }

    int warp = threadIdx.x >> 5, lane = threadIdx.x & 31;
    int nodebase = blockIdx.x * 64;

    for (int m = 0; m < 8; m++) {
        int nl = warp * 8 + m;
        int node = nodebase + nl;
        float ax0 = 0.f, ay0 = 0.f, ax1 = 0.f, ay1 = 0.f;
        float mx = 0.f, my = 0.f;
        if (node < N_NODESC) {
            int s = g_rowptr[node], e = g_rowptr[node + 1];
            int i = s;
            for (; i + 8 <= e; i += 8) {
                int s0 = __ldg(&g_src[i]);
                int s1 = __ldg(&g_src[i + 1]);
                int s2 = __ldg(&g_src[i + 2]);
                int s3 = __ldg(&g_src[i + 3]);
                int s4 = __ldg(&g_src[i + 4]);
                int s5 = __ldg(&g_src[i + 5]);
                int s6 = __ldg(&g_src[i + 6]);
                int s7 = __ldg(&g_src[i + 7]);
                float2 v0 = __half22float2(__ldg(&hin2[s0 * NH2 + lane]));
                float2 v1 = __half22float2(__ldg(&hin2[s1 * NH2 + lane]));
                float2 v2 = __half22float2(__ldg(&hin2[s2 * NH2 + lane]));
                float2 v3 = __half22float2(__ldg(&hin2[s3 * NH2 + lane]));
                float2 v4 = __half22float2(__ldg(&hin2[s4 * NH2 + lane]));
                float2 v5 = __half22float2(__ldg(&hin2[s5 * NH2 + lane]));
                float2 v6 = __half22float2(__ldg(&hin2[s6 * NH2 + lane]));
                float2 v7 = __half22float2(__ldg(&hin2[s7 * NH2 + lane]));
                ax0 += v0.x; ay0 += v0.y;
                ax1 += v1.x; ay1 += v1.y;
                ax0 += v2.x; ay0 += v2.y;
                ax1 += v3.x; ay1 += v3.y;
                ax0 += v4.x; ay0 += v4.y;
                ax1 += v5.x; ay1 += v5.y;
                ax0 += v6.x; ay0 += v6.y;
                ax1 += v7.x; ay1 += v7.y;
            }
            if (i + 4 <= e) {
                int s0 = __ldg(&g_src[i]);
                int s1 = __ldg(&g_src[i + 1]);
                int s2 = __ldg(&g_src[i + 2]);
                int s3 = __ldg(&g_src[i + 3]);
                float2 v0 = __half22float2(__ldg(&hin2[s0 * NH2 + lane]));
                float2 v1 = __half22float2(__ldg(&hin2[s1 * NH2 + lane]));
                float2 v2 = __half22float2(__ldg(&hin2[s2 * NH2 + lane]));
                float2 v3 = __half22float2(__ldg(&hin2[s3 * NH2 + lane]));
                ax0 += v0.x; ay0 += v0.y;
                ax1 += v1.x; ay1 += v1.y;
                ax0 += v2.x; ay0 += v2.y;
                ax1 += v3.x; ay1 += v3.y;
                i += 4;
            }
            for (; i < e; i++) {
                int s0 = __ldg(&g_src[i]);
                float2 v0 = __half22float2(__ldg(&hin2[s0 * NH2 + lane]));
                ax0 += v0.x; ay0 += v0.y;
            }
            float ax = ax0 + ax1, ay = ay0 + ay1;
            float2 h0v = __half22float2(__ldg(&h0h[node * NH2 + lane]));
            float dv = g_dinv[node];
            mx = fmaf(0.9f * dv, ax, 0.1f * h0v.x);
            my = fmaf(0.9f * dv, ay, 0.1f * h0v.y);
        }
        *(__half2*)&sMixA[nl * MIX_S + 2 * lane] = __floats2half2_rn(mx, my);
    }
    __syncthreads();

    int g = lane >> 2, t = lane & 3;
    int m0 = (warp & 3) * 16;
    int nu = warp >> 2;

    float d[2][2][4];
    #pragma unroll
    for (int u = 0; u < 2; u++)
        #pragma unroll
        for (int jm = 0; jm < 2; jm++)
            #pragma unroll
            for (int q = 0; q < 4; q++) d[u][jm][q] = 0.f;

    #pragma unroll
    for (int ks = 0; ks < 4; ks++) {
        int k0 = ks * 16;
        unsigned a0 = *(const unsigned*)&sMixA[(m0 + g) * MIX_S + k0 + 2 * t];
        unsigned a1 = *(const unsigned*)&sMixA[(m0 + g + 8) * MIX_S + k0 + 2 * t];
        unsigned a2 = *(const unsigned*)&sMixA[(m0 + g) * MIX_S + k0 + 2 * t + 8];
        unsigned a3 = *(const unsigned*)&sMixA[(m0 + g + 8) * MIX_S + k0 + 2 * t + 8];
        #pragma unroll
        for (int u = 0; u < 2; u++) {
            #pragma unroll
            for (int jm = 0; jm < 2; jm++) {
                int n8 = nu * 32 + u * 16 + jm * 8;
                unsigned b0 = *(const unsigned*)&sWT[(n8 + g) * MIX_S + k0 + 2 * t];
                unsigned b1 = *(const unsigned*)&sWT[(n8 + g) * MIX_S + k0 + 2 * t + 8];
                asm volatile(
                    "mma.sync.aligned.m16n8k16.row.col.f32.f16.f16.f32 "
                    "{%0,%1,%2,%3}, {%4,%5,%6,%7}, {%8,%9}, {%0,%1,%2,%3};"
                    : "+f"(d[u][jm][0]), "+f"(d[u][jm][1]),
                      "+f"(d[u][jm][2]), "+f"(d[u][jm][3])
                    : "r"(a0), "r"(a1), "r"(a2), "r"(a3), "r"(b0), "r"(b1));
            }
        }
    }

    int node0 = nodebase + m0 + g;
    int node1 = node0 + 8;
    float sc0 = 1.f, sc1 = 1.f;
    if (scale_out) {
        if (node0 < N_NODESC) sc0 = g_dinv[node0];
        if (node1 < N_NODESC) sc1 = g_dinv[node1];
    }
    #pragma unroll
    for (int u = 0; u < 2; u++) {
        #pragma unroll
        for (int jm = 0; jm < 2; jm++) {
            int j0 = nu * 32 + u * 16 + jm * 8 + 2 * t;
            if (node0 < N_NODESC) {
                float o0 = fmaxf(d[u][jm][0], 0.f) * sc0;
                float o1 = fmaxf(d[u][jm][1], 0.f) * sc0;
                hout2[node0 * NH2 + (j0 >> 1)] = __floats2half2_rn(o0, o1);
            }
            if (node1 < N_NODESC) {
                float o0 = fmaxf(d[u][jm][2], 0.f) * sc1;
                float o1 = fmaxf(d[u][jm][3], 0.f) * sc1;
                hout2[node1 * NH2 + (j0 >> 1)] = __floats2half2_rn(o0, o1);
            }
        }
    }
}

// ---------------- fc2: out = h @ W2^T + b2 via mma.sync (W2 zero-padded to 64 rows) ----------------
__global__ __launch_bounds__(256) void k_fc2(const __half2* __restrict__ hin2,
                                             const float* __restrict__ w,
                                             const float* __restrict__ b,
                                             float* __restrict__ out) {
    __shared__ __half sH[64 * MIX_S];       // 9.2 KB [node][k]
    __shared__ __half sW2[64 * MIX_S];      // 9.2 KB [j][k], rows 40..63 zero
    __shared__ float  sBias[64];

    int tid = threadIdx.x;
    int base = blockIdx.x * 64;

    // stage W2 (40x64 fp32 -> fp16), zero-pad rows 40..63
    for (int i = tid; i < 64 * NH; i += 256) {
        int j = i >> 6, k = i & 63;
        sW2[j * MIX_S + k] = (j < OUT_CHC) ? __float2half(w[j * NH + k]) : __half(0);
    }
    if (tid < 64) sBias[tid] = (tid < OUT_CHC) ? b[tid] : 0.f;
    // stage h tile (fp16 copy): 64 rows x 8 uint4
    {
        int row = tid >> 2, seg = tid & 3;
        int grow = (base + row < N_NODESC) ? (base + row) : (N_NODESC - 1);
        const uint4* src = (const uint4*)&hin2[grow * NH2];
        #pragma unroll
        for (int it = 0; it < 2; it++) {
            int u = seg + 4 * it;       // 0..7
            *(uint4*)&sH[row * MIX_S + u * 8] = __ldg(&src[u]);
        }
    }
    __syncthreads();

    int warp = tid >> 5, lane = tid & 31;
    int g = lane >> 2, t = lane & 3;
    int m0 = (warp & 3) * 16;
    int nu = warp >> 2;

    float d[2][2][4];
    #pragma unroll
    for (int u = 0; u < 2; u++)
        #pragma unroll
        for (int jm = 0; jm < 2; jm++)
            #pragma unroll
            for (int q = 0; q < 4; q++) d[u][jm][q] = 0.f;

    #pragma unroll
    for (int ks = 0; ks < 4; ks++) {
        int k0 = ks * 16;
        unsigned a0 = *(const unsigned*)&sH[(m0 + g) * MIX_S + k0 + 2 * t];
        unsigned a1 = *(const unsigned*)&sH[(m0 + g + 8) * MIX_S + k0 + 2 * t];
        unsigned a2 = *(const unsigned*)&sH[(m0 + g) * MIX_S + k0 + 2 * t + 8];
        unsigned a3 = *(const unsigned*)&sH[(m0 + g + 8) * MIX_S + k0 + 2 * t + 8];
        #pragma unroll
        for (int u = 0; u < 2; u++) {
            #pragma unroll
            for (int jm = 0; jm < 2; jm++) {
                int n8 = nu * 32 + u * 16 + jm * 8;
                unsigned b0 = *(const unsigned*)&sW2[(n8 + g) * MIX_S + k0 + 2 * t];
                unsigned b1 = *(const unsigned*)&sW2[(n8 + g) * MIX_S + k0 + 2 * t + 8];
                asm volatile(
                    "mma.sync.aligned.m16n8k16.row.col.f32.f16.f16.f32 "
                    "{%0,%1,%2,%3}, {%4,%5,%6,%7}, {%8,%9}, {%0,%1,%2,%3};"
                    : "+f"(d[u][jm][0]), "+f"(d[u][jm][1]),
                      "+f"(d[u][jm][2]), "+f"(d[u][jm][3])
                    : "r"(a0), "r"(a1), "r"(a2), "r"(a3), "r"(b0), "r"(b1));
            }
        }
    }

    int node0 = base + m0 + g;
    int node1 = node0 + 8;
    #pragma unroll
    for (int u = 0; u < 2; u++) {
        #pragma unroll
        for (int jm = 0; jm < 2; jm++) {
            int j0 = nu * 32 + u * 16 + jm * 8 + 2 * t;
            if (j0 < OUT_CHC) {
                float2 bb = *(const float2*)&sBias[j0];
                if (node0 < N_NODESC) {
                    *(float2*)&out[(long)node0 * OUT_CHC + j0] =
                        make_float2(d[u][jm][0] + bb.x, d[u][jm][1] + bb.y);
                }
                if (node1 < N_NODESC) {
                    *(float2*)&out[(long)node1 * OUT_CHC + j0] =
                        make_float2(d[u][jm][2] + bb.x, d[u][jm][3] + bb.y);
                }
            }
        }
    }
}

// ---------------- launch ----------------
extern "C" void kernel_launch(void* const* d_in, const int* in_sizes, int n_in,
                              void* d_out, int out_size) {
    const float* x      = (const float*)d_in[0];
    const int*   ei     = (const int*)d_in[1];
    const float* fc1_w  = (const float*)d_in[3];
    const float* fc1_b  = (const float*)d_in[4];
    const float* conv_w = (const float*)d_in[5];
    const float* fc2_w  = (const float*)d_in[6];
    const float* fc2_b  = (const float*)d_in[7];
    float*       out    = (float*)d_out;

    const int nb_nodes  = (N_NODESC + 255) / 256;
    const int nb_equads = (N_EDGESC / 4 + 255) / 256;

    k_init<<<nb_nodes, 256>>>(ei);              // 0
    k_degree<<<nb_equads, 256>>>(ei);           // 1
    k_scan_bsum<<<SCAN_NBLK, SCAN_CHUNK>>>();   // 2 (also dinv)
    k_fc1<<<1563, 256>>>(x, fc1_w, fc1_b);      // 3 (profiled slot)
    k_scan_top<<<1, 128>>>();
    k_scan_within<<<SCAN_NBLK, SCAN_CHUNK>>>();
    k_scatter<<<nb_equads, 256>>>(ei);

    __half2* h0h; __half2* h016; __half2* hA16; __half2* hB16;
    cudaGetSymbolAddress((void**)&h0h,  g_h0h);
    cudaGetSymbolAddress((void**)&h016, g_h016);
    cudaGetSymbolAddress((void**)&hA16, g_hA16);
    cudaGetSymbolAddress((void**)&hB16, g_hB16);

    const int nb_layer = (N_NODESC + 63) / 64;  // 1563
    k_layer<<<nb_layer, 256>>>(h016, h0h, conv_w + 0 * NH * NH, hA16, 1);
    k_layer<<<nb_layer, 256>>>(hA16, h0h, conv_w + 1 * NH * NH, hB16, 1);
    k_layer<<<nb_layer, 256>>>(hB16, h0h, conv_w + 2 * NH * NH, hA16, 1);
    k_layer<<<nb_layer, 256>>>(hA16, h0h, conv_w + 3 * NH * NH, hB16, 0);

    k_fc2<<<nb_layer, 256>>>(hB16, fc2_w, fc2_b, out);
}

// round 17
// speedup vs baseline: 1.2039x; 1.0037x over previous
#include <cuda_runtime.h>
#include <cuda_fp16.h>

#define N_NODESC 100000
#define N_EDGESC 1600000
#define IN_CH    128
#define NH       64
#define NH2      32
#define OUT_CHC  40

#define SCAN_CHUNK 1024
#define SCAN_NBLK  ((N_NODESC + SCAN_CHUNK - 1) / SCAN_CHUNK)   // 98

typedef unsigned long long u64b;

// ---------------- scratch ----------------
__device__ int     g_is64;
__device__ int     g_deg[N_NODESC];
__device__ int     g_rowptr[N_NODESC + 1];
__device__ int     g_cursor[N_NODESC];
__device__ int     g_bsum[SCAN_NBLK];
__device__ int     g_boff[SCAN_NBLK];
__device__ int     g_src[N_EDGESC + 8];
__device__ float   g_dinv[N_NODESC];
__device__ __half2 g_h0h[N_NODESC * NH2];        // fp16 residual (unscaled)
__device__ __half2 g_h016[N_NODESC * NH2];       // fp16, pre-scaled by dinv[node]
__device__ __half2 g_hA16[N_NODESC * NH2];
__device__ __half2 g_hB16[N_NODESC * NH2];

// ---------------- dtype detect (32 threads) ----------------
__global__ void k_detect(const int* __restrict__ ei) {
    int nz = 0;
    for (int j = threadIdx.x; j < 256; j += 32) nz |= ei[2 * j + 1];
    nz = __reduce_or_sync(0xffffffffu, nz);
    if (threadIdx.x == 0) g_is64 = (nz == 0) ? 1 : 0;
}

// 4 edges per thread; histogram only
__global__ void k_degree(const int* __restrict__ ei) {
    int t = blockIdx.x * blockDim.x + threadIdx.x;
    if (t >= N_EDGESC / 4) return;
    int c[4];
    if (g_is64) {
        int4 a = __ldg((const int4*)&ei[2 * N_EDGESC + 8 * t]);
        int4 b = __ldg((const int4*)&ei[2 * N_EDGESC + 8 * t + 4]);
        c[0] = a.x; c[1] = a.z; c[2] = b.x; c[3] = b.z;
    } else {
        int4 a = __ldg((const int4*)&ei[N_EDGESC + 4 * t]);
        c[0] = a.x; c[1] = a.y; c[2] = a.z; c[3] = a.w;
    }
    #pragma unroll
    for (int q = 0; q < 4; q++) {
        int cc = ((unsigned)c[q] >= N_NODESC) ? 0 : c[q];
        atomicAdd(&g_deg[cc], 1);
    }
}

// warp-shfl block scan: dinv + block-local exclusive (temp in g_cursor) + bsum
__global__ void k_scanA() {
    __shared__ int sWarp[32];
    int t = threadIdx.x;
    int i = blockIdx.x * SCAN_CHUNK + t;
    int lane = t & 31, wid = t >> 5;
    int d = (i < N_NODESC) ? g_deg[i] : 0;
    if (i < N_NODESC) g_dinv[i] = (d > 0) ? rsqrtf((float)d) : 0.0f;
    int val = d;
    #pragma unroll
    for (int off = 1; off < 32; off <<= 1) {
        int n = __shfl_up_sync(0xffffffffu, val, off);
        if (lane >= off) val += n;
    }
    if (lane == 31) sWarp[wid] = val;
    __syncthreads();
    if (wid == 0) {
        int wv = sWarp[lane];
        #pragma unroll
        for (int off = 1; off < 32; off <<= 1) {
            int n = __shfl_up_sync(0xffffffffu, wv, off);
            if (lane >= off) wv += n;
        }
        sWarp[lane] = wv;
    }
    __syncthreads();
    int wexcl = (wid == 0) ? 0 : sWarp[wid - 1];
    if (i < N_NODESC) g_cursor[i] = val - d + wexcl;
    if (t == 0) g_bsum[blockIdx.x] = sWarp[31];
}

__global__ void k_scan_top() {
    __shared__ int s[128];
    int t = threadIdx.x;
    s[t] = (t < SCAN_NBLK) ? g_bsum[t] : 0;
    __syncthreads();
    if (t == 0) {
        int acc = 0;
        for (int b = 0; b < SCAN_NBLK; b++) { int v = s[b]; s[b] = acc; acc += v; }
        g_rowptr[N_NODESC] = N_EDGESC;
    }
    __syncthreads();
    if (t < SCAN_NBLK) g_boff[t] = s[t];
}

// add block offsets, finalize rowptr + cursor
__global__ void k_scanB() {
    int i = blockIdx.x * SCAN_CHUNK + threadIdx.x;
    if (i < N_NODESC) {
        int excl = g_cursor[i] + g_boff[blockIdx.x];
        g_rowptr[i] = excl;
        g_cursor[i] = excl;
    }
}

// 4 edges per thread directly from ei; src index only
__global__ void k_scatter(const int* __restrict__ ei) {
    int t = blockIdx.x * blockDim.x + threadIdx.x;
    if (t >= N_EDGESC / 4) return;
    int r[4], c[4];
    if (g_is64) {
        int4 ra = __ldg((const int4*)&ei[8 * t]);
        int4 rb = __ldg((const int4*)&ei[8 * t + 4]);
        int4 ca = __ldg((const int4*)&ei[2 * N_EDGESC + 8 * t]);
        int4 cb = __ldg((const int4*)&ei[2 * N_EDGESC + 8 * t + 4]);
        r[0] = ra.x; r[1] = ra.z; r[2] = rb.x; r[3] = rb.z;
        c[0] = ca.x; c[1] = ca.z; c[2] = cb.x; c[3] = cb.z;
    } else {
        int4 ra = __ldg((const int4*)&ei[4 * t]);
        int4 ca = __ldg((const int4*)&ei[N_EDGESC + 4 * t]);
        r[0] = ra.x; r[1] = ra.y; r[2] = ra.z; r[3] = ra.w;
        c[0] = ca.x; c[1] = ca.y; c[2] = ca.z; c[3] = ca.w;
    }
    #pragma unroll
    for (int q = 0; q < 4; q++) {
        int rr = ((unsigned)r[q] >= N_NODESC) ? 0 : r[q];
        int cc = ((unsigned)c[q] >= N_NODESC) ? 0 : c[q];
        int p = atomicAdd(&g_cursor[cc], 1);
        if ((unsigned)p < N_EDGESC) g_src[p] = rr;
    }
}

// ---------------- fc1: h = relu(x @ W1^T + b1) via mma.sync fp16 (R14 exact) ----------------
#define FC1_XS 136
__global__ __launch_bounds__(256) void k_fc1(const float* __restrict__ x,
                                             const float* __restrict__ w,
                                             const float* __restrict__ b) {
    __shared__ __half sX[64 * FC1_XS];
    __shared__ __half sW[64 * FC1_XS];
    __shared__ float  sBias[NH];
    __shared__ float  sDinv[64];

    int tid = threadIdx.x;
    int base = blockIdx.x * 64;

    {
        int row = tid >> 2, seg = tid & 3;
        #pragma unroll
        for (int it = 0; it < 4; it++) {
            int k = seg * 32 + it * 8;
            float4 v0 = __ldg((const float4*)&w[row * IN_CH + k]);
            float4 v1 = __ldg((const float4*)&w[row * IN_CH + k + 4]);
            __half2 h0 = __floats2half2_rn(v0.x, v0.y);
            __half2 h1 = __floats2half2_rn(v0.z, v0.w);
            __half2 h2 = __floats2half2_rn(v1.x, v1.y);
            __half2 h3 = __floats2half2_rn(v1.z, v1.w);
            uint4 u = make_uint4(*(unsigned*)&h0, *(unsigned*)&h1,
                                 *(unsigned*)&h2, *(unsigned*)&h3);
            *(uint4*)&sW[row * FC1_XS + k] = u;
        }
    }
    {
        int row = tid >> 2, seg = tid & 3;
        long grow = (base + row < N_NODESC) ? (long)(base + row) : (long)(N_NODESC - 1);
        #pragma unroll
        for (int it = 0; it < 4; it++) {
            int k = seg * 32 + it * 8;
            float4 v0 = __ldg((const float4*)&x[grow * IN_CH + k]);
            float4 v1 = __ldg((const float4*)&x[grow * IN_CH + k + 4]);
            __half2 h0 = __floats2half2_rn(v0.x, v0.y);
            __half2 h1 = __floats2half2_rn(v0.z, v0.w);
            __half2 h2 = __floats2half2_rn(v1.x, v1.y);
            __half2 h3 = __floats2half2_rn(v1.z, v1.w);
            uint4 u = make_uint4(*(unsigned*)&h0, *(unsigned*)&h1,
                                 *(unsigned*)&h2, *(unsigned*)&h3);
            *(uint4*)&sX[row * FC1_XS + k] = u;
        }
    }
    if (tid < NH) sBias[tid] = b[tid];
    if (tid < 64) sDinv[tid] = (base + tid < N_NODESC) ? g_dinv[base + tid] : 0.f;
    __syncthreads();

    int warp = tid >> 5, lane = tid & 31;
    int g = lane >> 2, t = lane & 3;
    int m0 = (warp & 3) * 16;
    int nu = warp >> 2;

    float d[2][2][4];
    #pragma unroll
    for (int u = 0; u < 2; u++)
        #pragma unroll
        for (int jm = 0; jm < 2; jm++)
            #pragma unroll
            for (int q = 0; q < 4; q++) d[u][jm][q] = 0.f;

    #pragma unroll
    for (int ks = 0; ks < 8; ks++) {
        int k0 = ks * 16;
        unsigned a0 = *(const unsigned*)&sX[(m0 + g) * FC1_XS + k0 + 2 * t];
        unsigned a1 = *(const unsigned*)&sX[(m0 + g + 8) * FC1_XS + k0 + 2 * t];
        unsigned a2 = *(const unsigned*)&sX[(m0 + g) * FC1_XS + k0 + 2 * t + 8];
        unsigned a3 = *(const unsigned*)&sX[(m0 + g + 8) * FC1_XS + k0 + 2 * t + 8];
        #pragma unroll
        for (int u = 0; u < 2; u++) {
            #pragma unroll
            for (int jm = 0; jm < 2; jm++) {
                int n8 = nu * 32 + u * 16 + jm * 8;
                unsigned b0 = *(const unsigned*)&sW[(n8 + g) * FC1_XS + k0 + 2 * t];
                unsigned b1 = *(const unsigned*)&sW[(n8 + g) * FC1_XS + k0 + 2 * t + 8];
                asm volatile(
                    "mma.sync.aligned.m16n8k16.row.col.f32.f16.f16.f32 "
                    "{%0,%1,%2,%3}, {%4,%5,%6,%7}, {%8,%9}, {%0,%1,%2,%3};"
                    : "+f"(d[u][jm][0]), "+f"(d[u][jm][1]),
                      "+f"(d[u][jm][2]), "+f"(d[u][jm][3])
                    : "r"(a0), "r"(a1), "r"(a2), "r"(a3), "r"(b0), "r"(b1));
            }
        }
    }

    int node0 = base + m0 + g;
    int node1 = node0 + 8;
    float dv0 = sDinv[m0 + g], dv1 = sDinv[m0 + g + 8];
    #pragma unroll
    for (int u = 0; u < 2; u++) {
        #pragma unroll
        for (int jm = 0; jm < 2; jm++) {
            int j0 = nu * 32 + u * 16 + jm * 8 + 2 * t;
            float2 bb = *(const float2*)&sBias[j0];
            float r00 = fmaxf(d[u][jm][0] + bb.x, 0.f);
            float r01 = fmaxf(d[u][jm][1] + bb.y, 0.f);
            float r10 = fmaxf(d[u][jm][2] + bb.x, 0.f);
            float r11 = fmaxf(d[u][jm][3] + bb.y, 0.f);
            if (node0 < N_NODESC) {
                g_h0h[node0 * NH2 + (j0 >> 1)]  = __floats2half2_rn(r00, r01);
                g_h016[node0 * NH2 + (j0 >> 1)] = __floats2half2_rn(r00 * dv0, r01 * dv0);
            }
            if (node1 < N_NODESC) {
                g_h0h[node1 * NH2 + (j0 >> 1)]  = __floats2half2_rn(r10, r11);
                g_h016[node1 * NH2 + (j0 >> 1)] = __floats2half2_rn(r10 * dv1, r11 * dv1);
            }
        }
    }
}

// ---------------- fused GCN2 layer: R14 exact (gather FROZEN, mma matmul) ----------------
#define MIX_S 72
__global__ __launch_bounds__(256) void k_layer(const __half2* __restrict__ hin2,
                                               const __half2* __restrict__ h0h,
                                               const float* __restrict__ W,
                                               __half2* __restrict__ hout2,
                                               int scale_out) {
    __shared__ __half sMixA[64 * MIX_S];
    __shared__ __half sWT[64 * MIX_S];

    for (int i = threadIdx.x; i < NH * NH; i += 256) {
        int k = i >> 6, j = i & 63;
        sWT[j * MIX_S + k] = __float2half(W[i]);
    }

    int warp = threadIdx.x >> 5, lane = threadIdx.x & 31;
    int nodebase = blockIdx.x * 64;

    for (int m = 0; m < 8; m++) {
        int nl = warp * 8 + m;
        int node = nodebase + nl;
        float ax0 = 0.f, ay0 = 0.f, ax1 = 0.f, ay1 = 0.f;
        float mx = 0.f, my = 0.f;
        if (node < N_NODESC) {
            int s = g_rowptr[node], e = g_rowptr[node + 1];
            int i = s;
            for (; i + 8 <= e; i += 8) {
                int s0 = __ldg(&g_src[i]);
                int s1 = __ldg(&g_src[i + 1]);
                int s2 = __ldg(&g_src[i + 2]);
                int s3 = __ldg(&g_src[i + 3]);
                int s4 = __ldg(&g_src[i + 4]);
                int s5 = __ldg(&g_src[i + 5]);
                int s6 = __ldg(&g_src[i + 6]);
                int s7 = __ldg(&g_src[i + 7]);
                float2 v0 = __half22float2(__ldg(&hin2[s0 * NH2 + lane]));
                float2 v1 = __half22float2(__ldg(&hin2[s1 * NH2 + lane]));
                float2 v2 = __half22float2(__ldg(&hin2[s2 * NH2 + lane]));
                float2 v3 = __half22float2(__ldg(&hin2[s3 * NH2 + lane]));
                float2 v4 = __half22float2(__ldg(&hin2[s4 * NH2 + lane]));
                float2 v5 = __half22float2(__ldg(&hin2[s5 * NH2 + lane]));
                float2 v6 = __half22float2(__ldg(&hin2[s6 * NH2 + lane]));
                float2 v7 = __half22float2(__ldg(&hin2[s7 * NH2 + lane]));
                ax0 += v0.x; ay0 += v0.y;
                ax1 += v1.x; ay1 += v1.y;
                ax0 += v2.x; ay0 += v2.y;
                ax1 += v3.x; ay1 += v3.y;
                ax0 += v4.x; ay0 += v4.y;
                ax1 += v5.x; ay1 += v5.y;
                ax0 += v6.x; ay0 += v6.y;
                ax1 += v7.x; ay1 += v7.y;
            }
            if (i + 4 <= e) {
                int s0 = __ldg(&g_src[i]);
                int s1 = __ldg(&g_src[i + 1]);
                int s2 = __ldg(&g_src[i + 2]);
                int s3 = __ldg(&g_src[i + 3]);
                float2 v0 = __half22float2(__ldg(&hin2[s0 * NH2 + lane]));
                float2 v1 = __half22float2(__ldg(&hin2[s1 * NH2 + lane]));
                float2 v2 = __half22float2(__ldg(&hin2[s2 * NH2 + lane]));
                float2 v3 = __half22float2(__ldg(&hin2[s3 * NH2 + lane]));
                ax0 += v0.x; ay0 += v0.y;
                ax1 += v1.x; ay1 += v1.y;
                ax0 += v2.x; ay0 += v2.y;
                ax1 += v3.x; ay1 += v3.y;
                i += 4;
            }
            for (; i < e; i++) {
                int s0 = __ldg(&g_src[i]);
                float2 v0 = __half22float2(__ldg(&hin2[s0 * NH2 + lane]));
                ax0 += v0.x; ay0 += v0.y;
            }
            float ax = ax0 + ax1, ay = ay0 + ay1;
            float2 h0v = __half22float2(__ldg(&h0h[node * NH2 + lane]));
            float dv = g_dinv[node];
            mx = fmaf(0.9f * dv, ax, 0.1f * h0v.x);
            my = fmaf(0.9f * dv, ay, 0.1f * h0v.y);
        }
        *(__half2*)&sMixA[nl * MIX_S + 2 * lane] = __floats2half2_rn(mx, my);
    }
    __syncthreads();

    int g = lane >> 2, t = lane & 3;
    int m0 = (warp & 3) * 16;
    int nu = warp >> 2;

    float d[2][2][4];
    #pragma unroll
    for (int u = 0; u < 2; u++)
        #pragma unroll
        for (int jm = 0; jm < 2; jm++)
            #pragma unroll
            for (int q = 0; q < 4; q++) d[u][jm][q] = 0.f;

    #pragma unroll
    for (int ks = 0; ks < 4; ks++) {
        int k0 = ks * 16;
        unsigned a0 = *(const unsigned*)&sMixA[(m0 + g) * MIX_S + k0 + 2 * t];
        unsigned a1 = *(const unsigned*)&sMixA[(m0 + g + 8) * MIX_S + k0 + 2 * t];
        unsigned a2 = *(const unsigned*)&sMixA[(m0 + g) * MIX_S + k0 + 2 * t + 8];
        unsigned a3 = *(const unsigned*)&sMixA[(m0 + g + 8) * MIX_S + k0 + 2 * t + 8];
        #pragma unroll
        for (int u = 0; u < 2; u++) {
            #pragma unroll
            for (int jm = 0; jm < 2; jm++) {
                int n8 = nu * 32 + u * 16 + jm * 8;
                unsigned b0 = *(const unsigned*)&sWT[(n8 + g) * MIX_S + k0 + 2 * t];
                unsigned b1 = *(const unsigned*)&sWT[(n8 + g) * MIX_S + k0 + 2 * t + 8];
                asm volatile(
                    "mma.sync.aligned.m16n8k16.row.col.f32.f16.f16.f32 "
                    "{%0,%1,%2,%3}, {%4,%5,%6,%7}, {%8,%9}, {%0,%1,%2,%3};"
                    : "+f"(d[u][jm][0]), "+f"(d[u][jm][1]),
                      "+f"(d[u][jm][2]), "+f"(d[u][jm][3])
                    : "r"(a0), "r"(a1), "r"(a2), "r"(a3), "r"(b0), "r"(b1));
            }
        }
    }

    int node0 = nodebase + m0 + g;
    int node1 = node0 + 8;
    float sc0 = 1.f, sc1 = 1.f;
    if (scale_out) {
        if (node0 < N_NODESC) sc0 = g_dinv[node0];
        if (node1 < N_NODESC) sc1 = g_dinv[node1];
    }
    #pragma unroll
    for (int u = 0; u < 2; u++) {
        #pragma unroll
        for (int jm = 0; jm < 2; jm++) {
            int j0 = nu * 32 + u * 16 + jm * 8 + 2 * t;
            if (node0 < N_NODESC) {
                float o0 = fmaxf(d[u][jm][0], 0.f) * sc0;
                float o1 = fmaxf(d[u][jm][1], 0.f) * sc0;
                hout2[node0 * NH2 + (j0 >> 1)] = __floats2half2_rn(o0, o1);
            }
            if (node1 < N_NODESC) {
                float o0 = fmaxf(d[u][jm][2], 0.f) * sc1;
                float o1 = fmaxf(d[u][jm][3], 0.f) * sc1;
                hout2[node1 * NH2 + (j0 >> 1)] = __floats2half2_rn(o0, o1);
            }
        }
    }
}

// ---------------- fc2: out = h @ W2^T + b2 via mma.sync (W2 zero-padded to 64 rows) ----------------
__global__ __launch_bounds__(256) void k_fc2(const __half2* __restrict__ hin2,
                                             const float* __restrict__ w,
                                             const float* __restrict__ b,
                                             float* __restrict__ out) {
    __shared__ __half sH[64 * MIX_S];
    __shared__ __half sW2[64 * MIX_S];
    __shared__ float  sBias[64];

    int tid = threadIdx.x;
    int base = blockIdx.x * 64;

    for (int i = tid; i < 64 * NH; i += 256) {
        int j = i >> 6, k = i & 63;
        sW2[j * MIX_S + k] = (j < OUT_CHC) ? __float2half(w[j * NH + k]) : __half(0);
    }
    if (tid < 64) sBias[tid] = (tid < OUT_CHC) ? b[tid] : 0.f;
    {
        int row = tid >> 2, seg = tid & 3;
        int grow = (base + row < N_NODESC) ? (base + row) : (N_NODESC - 1);
        const uint4* src = (const uint4*)&hin2[grow * NH2];
        #pragma unroll
        for (int it = 0; it < 2; it++) {
            int u = seg + 4 * it;
            *(uint4*)&sH[row * MIX_S + u * 8] = __ldg(&src[u]);
        }
    }
    __syncthreads();

    int warp = tid >> 5, lane = tid & 31;
    int g = lane >> 2, t = lane & 3;
    int m0 = (warp & 3) * 16;
    int nu = warp >> 2;

    float d[2][2][4];
    #pragma unroll
    for (int u = 0; u < 2; u++)
        #pragma unroll
        for (int jm = 0; jm < 2; jm++)
            #pragma unroll
            for (int q = 0; q < 4; q++) d[u][jm][q] = 0.f;

    #pragma unroll
    for (int ks = 0; ks < 4; ks++) {
        int k0 = ks * 16;
        unsigned a0 = *(const unsigned*)&sH[(m0 + g) * MIX_S + k0 + 2 * t];
        unsigned a1 = *(const unsigned*)&sH[(m0 + g + 8) * MIX_S + k0 + 2 * t];
        unsigned a2 = *(const unsigned*)&sH[(m0 + g) * MIX_S + k0 + 2 * t + 8];
        unsigned a3 = *(const unsigned*)&sH[(m0 + g + 8) * MIX_S + k0 + 2 * t + 8];
        #pragma unroll
        for (int u = 0; u < 2; u++) {
            #pragma unroll
            for (int jm = 0; jm < 2; jm++) {
                int n8 = nu * 32 + u * 16 + jm * 8;
                unsigned b0 = *(const unsigned*)&sW2[(n8 + g) * MIX_S + k0 + 2 * t];
                unsigned b1 = *(const unsigned*)&sW2[(n8 + g) * MIX_S + k0 + 2 * t + 8];
                asm volatile(
                    "mma.sync.aligned.m16n8k16.row.col.f32.f16.f16.f32 "
                    "{%0,%1,%2,%3}, {%4,%5,%6,%7}, {%8,%9}, {%0,%1,%2,%3};"
                    : "+f"(d[u][jm][0]), "+f"(d[u][jm][1]),
                      "+f"(d[u][jm][2]), "+f"(d[u][jm][3])
                    : "r"(a0), "r"(a1), "r"(a2), "r"(a3), "r"(b0), "r"(b1));
            }
        }
    }

    int node0 = base + m0 + g;
    int node1 = node0 + 8;
    #pragma unroll
    for (int u = 0; u < 2; u++) {
        #pragma unroll
        for (int jm = 0; jm < 2; jm++) {
            int j0 = nu * 32 + u * 16 + jm * 8 + 2 * t;
            if (j0 < OUT_CHC) {
                float2 bb = *(const float2*)&sBias[j0];
                if (node0 < N_NODESC) {
                    *(float2*)&out[(long)node0 * OUT_CHC + j0] =
                        make_float2(d[u][jm][0] + bb.x, d[u][jm][1] + bb.y);
                }
                if (node1 < N_NODESC) {
                    *(float2*)&out[(long)node1 * OUT_CHC + j0] =
                        make_float2(d[u][jm][2] + bb.x, d[u][jm][3] + bb.y);
                }
            }
        }
    }
}

// ---------------- launch ----------------
extern "C" void kernel_launch(void* const* d_in, const int* in_sizes, int n_in,
                              void* d_out, int out_size) {
    const float* x      = (const float*)d_in[0];
    const int*   ei     = (const int*)d_in[1];
    const float* fc1_w  = (const float*)d_in[3];
    const float* fc1_b  = (const float*)d_in[4];
    const float* conv_w = (const float*)d_in[5];
    const float* fc2_w  = (const float*)d_in[6];
    const float* fc2_b  = (const float*)d_in[7];
    float*       out    = (float*)d_out;

    const int nb_equads = (N_EDGESC / 4 + 255) / 256;

    void* degp;
    cudaGetSymbolAddress(&degp, g_deg);
    cudaMemsetAsync(degp, 0, N_NODESC * sizeof(int));

    k_detect<<<1, 32>>>(ei);
    k_degree<<<nb_equads, 256>>>(ei);
    k_scanA<<<SCAN_NBLK, SCAN_CHUNK>>>();       // dinv + block-local scan
    k_fc1<<<1563, 256>>>(x, fc1_w, fc1_b);      // profiled slot
    k_scan_top<<<1, 128>>>();
    k_scanB<<<SCAN_NBLK, SCAN_CHUNK>>>();
    k_scatter<<<nb_equads, 256>>>(ei);

    __half2* h0h; __half2* h016; __half2* hA16; __half2* hB16;
    cudaGetSymbolAddress((void**)&h0h,  g_h0h);
    cudaGetSymbolAddress((void**)&h016, g_h016);
    cudaGetSymbolAddress((void**)&hA16, g_hA16);
    cudaGetSymbolAddress((void**)&hB16, g_hB16);

    const int nb_layer = (N_NODESC + 63) / 64;  // 1563
    k_layer<<<nb_layer, 256>>>(h016, h0h, conv_w + 0 * NH * NH, hA16, 1);
    k_layer<<<nb_layer, 256>>>(hA16, h0h, conv_w + 1 * NH * NH, hB16, 1);
    k_layer<<<nb_layer, 256>>>(hB16, h0h, conv_w + 2 * NH * NH, hA16, 1);
    k_layer<<<nb_layer, 256>>>(hA16, h0h, conv_w + 3 * NH * NH, hB16, 0);

    k_fc2<<<nb_layer, 256>>>(hB16, fc2_w, fc2_b, out);
}